// round 15
// baseline (speedup 1.0000x reference)
#include <cuda_runtime.h>
#include <cuda_fp16.h>
#include <math.h>
#include <stdint.h>

#define NPATCH 8192
#define NPAD   (NPATCH + 128)
#define KC     10
#define DIN    1024
#define DH     512
#define DA     256
#define NCLS   4

// ---------------- device scratch (ONLY referenced inside device code) ----------------
__device__ int   g_cnt[KC];
__device__ int   g_off[KC + 1];
__device__ int   g_order[NPATCH];
__device__ __align__(128) __half g_w1t[(size_t)KC * DH * DIN];
__device__ __align__(128) __half g_w2t[(size_t)KC * DH * DH];
__device__ __align__(128) __half g_h1 [(size_t)NPAD * DH];
__device__ float g_psum[KC * DH];
__device__ float g_hs[KC * DH];
__device__ float g_Alog[KC];

// ---------------- PTX helpers ----------------
__device__ __forceinline__ uint32_t smem_u32(const void* p) {
    uint32_t a;
    asm("{ .reg .u64 t; cvta.to.shared.u64 t, %1; cvt.u32.u64 %0, t; }" : "=r"(a) : "l"(p));
    return a;
}
#define CPASYNC16(dst, src) asm volatile("cp.async.ca.shared.global [%0], [%1], 16;" :: "r"(dst), "l"(src) : "memory")
#define CP_COMMIT()         asm volatile("cp.async.commit_group;" ::: "memory")
#define CP_WAIT(n)          asm volatile("cp.async.wait_group %0;" :: "n"(n) : "memory")

__device__ __forceinline__ void ldsm4(uint32_t& r0, uint32_t& r1, uint32_t& r2, uint32_t& r3,
                                      uint32_t addr) {
    asm volatile("ldmatrix.sync.aligned.m8n8.x4.shared.b16 {%0,%1,%2,%3}, [%4];"
                 : "=r"(r0), "=r"(r1), "=r"(r2), "=r"(r3) : "r"(addr));
}
__device__ __forceinline__ void mma_f16(float* c, uint32_t a0, uint32_t a1, uint32_t a2,
                                        uint32_t a3, uint32_t b0, uint32_t b1) {
    asm volatile("mma.sync.aligned.m16n8k16.row.col.f32.f16.f16.f32 "
                 "{%0,%1,%2,%3}, {%4,%5,%6,%7}, {%8,%9}, {%0,%1,%2,%3};"
                 : "+f"(c[0]), "+f"(c[1]), "+f"(c[2]), "+f"(c[3])
                 : "r"(a0), "r"(a1), "r"(a2), "r"(a3), "r"(b0), "r"(b1));
}
__device__ __forceinline__ uint32_t packh2(float a, float b) {
    __half2 h = __floats2half2_rn(a, b);
    return *(uint32_t*)&h;
}

// ---------------- fused prep: hist + offsets + scatter + zero psum (single block) ----------
__global__ __launch_bounds__(1024) void k_prep(const int* __restrict__ cid, int n) {
    __shared__ int scnt[KC];
    __shared__ int scur[KC];
    int tid = threadIdx.x;
    if (tid < KC) scnt[tid] = 0;
    __syncthreads();
    for (int i = tid; i < n; i += 1024) atomicAdd(&scnt[cid[i]], 1);
    __syncthreads();
    if (tid == 0) {
        int s = 0;
        g_off[0] = 0;
        for (int k = 0; k < KC; k++) {
            g_cnt[k] = scnt[k];
            scur[k] = s;
            s += scnt[k];
            g_off[k + 1] = s;
        }
    }
    __syncthreads();
    for (int i = tid; i < n; i += 1024) {
        int c = cid[i];
        int pos = atomicAdd(&scur[c], 1);
        g_order[pos] = i;
    }
    for (int i = tid; i < KC * DH; i += 1024) g_psum[i] = 0.f;
}

// fused transpose+convert of BOTH weight tensors in one launch
// blockIdx.x in [0,32): W1 k-tile; [32,48): W2 k-tile. blockIdx.y: n-tile (16). z: cluster.
__global__ void k_conv_w_all(const float* __restrict__ W1, const float* __restrict__ W2) {
    int bx = blockIdx.x;
    int isW1 = bx < 32;
    const int KD = isW1 ? DIN : DH;
    const float* W = isW1 ? W1 : W2;
    __half* out = isW1 ? g_w1t : g_w2t;
    int kk0 = (isW1 ? bx : bx - 32) * 32;

    __shared__ float t[32][33];
    int tx = threadIdx.x, ty = threadIdx.y;
    int n0 = blockIdx.y * 32, k = blockIdx.z;
    const float* src = W + (size_t)k * KD * DH;
#pragma unroll
    for (int i = 0; i < 4; i++) {
        int row = ty + i * 8;
        t[row][tx] = src[(size_t)(kk0 + row) * DH + n0 + tx];
    }
    __syncthreads();
    __half* dst = out + (size_t)k * DH * KD;
#pragma unroll
    for (int i = 0; i < 4; i++) {
        int row = ty + i * 8;
        dst[(size_t)(n0 + row) * KD + kk0 + tx] = __float2half_rn(t[tx][row]);
    }
}

// ---------------- HMMA grouped GEMM ----------------
// EPI = 0: A = fp32 x gathered+converted in-loader; out g_h1 = fp16(relu(acc+bias))
// EPI = 1: A = g_h1 (fp16, cp.async);           out psum += colsum(relu(acc+bias))
#define LDA 40

template <int KDIM, int EPI>
__global__ __launch_bounds__(256, 2) void k_mma(const float* __restrict__ bias,
                                                const float* __restrict__ xsrc) {
    const __half* Bsrc = (EPI == 0) ? g_w1t : g_w2t;

    int k = blockIdx.z;
    int rend = g_off[k + 1];
    int row0 = g_off[k] + blockIdx.y * 128;
    if (row0 >= rend) return;
    int col0 = blockIdx.x * 128;

    __shared__ __align__(16) __half sA[2][128 * LDA];
    __shared__ __align__(16) __half sB[2][128 * LDA];

    int tid = threadIdx.x;
    int wid = tid >> 5, lane = tid & 31;
    int warp_m = wid & 1;
    int warp_n = wid >> 1;

    float acc[4][4][4];
#pragma unroll
    for (int mf = 0; mf < 4; mf++)
#pragma unroll
        for (int nf = 0; nf < 4; nf++)
#pragma unroll
            for (int q = 0; q < 4; q++) acc[mf][nf][q] = 0.f;

    int lrow = tid >> 1, lhalf = tid & 1;
    uint32_t aSm[2] = {smem_u32(&sA[0][0]), smem_u32(&sA[1][0])};
    uint32_t bSm[2] = {smem_u32(&sB[0][0]), smem_u32(&sB[1][0])};

    // B loader (cp.async), same for both
    uint32_t ldOff[2];
    const __half* bSrcQ[2];
#pragma unroll
    for (int q = 0; q < 2; q++) {
        int seg = lhalf * 2 + q;
        ldOff[q] = (uint32_t)(lrow * LDA + seg * 8) * 2;
        bSrcQ[q] = Bsrc + ((size_t)k * DH + col0 + lrow) * KDIM + seg * 8;
    }

    // A loader sources
    int arow = row0 + lrow;
    int arow_cl = (arow < rend) ? arow : (rend - 1);
    const float4* xq = nullptr;       // EPI==0: fp32 gathered
    const __half* aSrcQ[2] = {nullptr, nullptr};  // EPI==1: fp16 direct
    if (EPI == 0) {
        xq = (const float4*)(xsrc + (size_t)g_order[arow_cl] * DIN + lhalf * 16);
    } else {
#pragma unroll
        for (int q = 0; q < 2; q++) {
            int seg = lhalf * 2 + q;
            aSrcQ[q] = g_h1 + (size_t)arow * KDIM + seg * 8;
        }
    }
    __half* aSts = &sA[0][0] + (lrow * LDA + lhalf * 16);   // buf0 base; buf1 = +128*LDA

    int lane15 = lane & 15, lanehi = lane >> 4;
    uint32_t offA[4], offB[2];
#pragma unroll
    for (int mf = 0; mf < 4; mf++)
        offA[mf] = (uint32_t)((warp_m * 64 + mf * 16 + lane15) * LDA + lanehi * 8) * 2;
#pragma unroll
    for (int ng = 0; ng < 2; ng++)
        offB[ng] = (uint32_t)((warp_n * 32 + ng * 16 + lane15) * LDA + lanehi * 8) * 2;

    const int NCH = KDIM / 32;

    auto compute = [&](int buf) {
#pragma unroll
        for (int ks = 0; ks < 2; ks++) {
            uint32_t kof = ks * 32;
            uint32_t afr[4][4], bfr[4][2];
#pragma unroll
            for (int mf = 0; mf < 4; mf++)
                ldsm4(afr[mf][0], afr[mf][1], afr[mf][2], afr[mf][3], aSm[buf] + offA[mf] + kof);
#pragma unroll
            for (int ng = 0; ng < 2; ng++) {
                uint32_t r0, r1, r2, r3;
                ldsm4(r0, r1, r2, r3, bSm[buf] + offB[ng] + kof);
                bfr[ng * 2 + 0][0] = r0; bfr[ng * 2 + 0][1] = r2;
                bfr[ng * 2 + 1][0] = r1; bfr[ng * 2 + 1][1] = r3;
            }
#pragma unroll
            for (int mf = 0; mf < 4; mf++)
#pragma unroll
                for (int nf = 0; nf < 4; nf++)
                    mma_f16(acc[mf][nf], afr[mf][0], afr[mf][1], afr[mf][2], afr[mf][3],
                            bfr[nf][0], bfr[nf][1]);
        }
    };

    if (EPI == 0) {
        // ---- A: fp32 LDG + convert + STS (register prefetch); B: cp.async ----
        float4 fa[4];
#pragma unroll
        for (int q = 0; q < 4; q++) fa[q] = __ldg(xq + q);
#pragma unroll
        for (int q = 0; q < 2; q++) CPASYNC16(bSm[0] + ldOff[q], bSrcQ[q]);
        CP_COMMIT();

        for (int s = 0; s < NCH; s++) {
            int buf = s & 1;
            {   // convert + store current A chunk
                uint32_t hw[8];
#pragma unroll
                for (int q = 0; q < 4; q++) {
                    hw[2 * q + 0] = packh2(fa[q].x, fa[q].y);
                    hw[2 * q + 1] = packh2(fa[q].z, fa[q].w);
                }
                uint4* d = (uint4*)(aSts + buf * 128 * LDA);
                d[0] = make_uint4(hw[0], hw[1], hw[2], hw[3]);
                d[1] = make_uint4(hw[4], hw[5], hw[6], hw[7]);
            }
            if (s + 1 < NCH) {
                int nb = (s + 1) & 1;
#pragma unroll
                for (int q = 0; q < 2; q++)
                    CPASYNC16(bSm[nb] + ldOff[q], bSrcQ[q] + (size_t)(s + 1) * 32);
                CP_COMMIT();
                CP_WAIT(1);
            } else {
                CP_WAIT(0);
            }
            __syncthreads();
            if (s + 1 < NCH) {
#pragma unroll
                for (int q = 0; q < 4; q++) fa[q] = __ldg(xq + (s + 1) * 8 + q);
            }
            compute(buf);
            __syncthreads();
        }
    } else {
        // ---- both A and B via cp.async (A rows already cluster-sorted in g_h1) ----
#pragma unroll
        for (int q = 0; q < 2; q++) {
            CPASYNC16(aSm[0] + ldOff[q], aSrcQ[q]);
            CPASYNC16(bSm[0] + ldOff[q], bSrcQ[q]);
        }
        CP_COMMIT();

        for (int s = 0; s < NCH; s++) {
            int buf = s & 1;
            if (s + 1 < NCH) {
                int nb = (s + 1) & 1;
#pragma unroll
                for (int q = 0; q < 2; q++) {
                    CPASYNC16(aSm[nb] + ldOff[q], aSrcQ[q] + (size_t)(s + 1) * 32);
                    CPASYNC16(bSm[nb] + ldOff[q], bSrcQ[q] + (size_t)(s + 1) * 32);
                }
                CP_COMMIT();
                CP_WAIT(1);
            } else {
                CP_WAIT(0);
            }
            __syncthreads();
            compute(buf);
            __syncthreads();
        }
    }

    // ---------------- epilogue ----------------
    const float* bp = bias + k * DH + col0 + warp_n * 32;
    float bv[4][2];
#pragma unroll
    for (int nf = 0; nf < 4; nf++) {
        bv[nf][0] = __ldg(bp + nf * 8 + (lane & 3) * 2);
        bv[nf][1] = __ldg(bp + nf * 8 + (lane & 3) * 2 + 1);
    }
    int rbase = row0 + warp_m * 64 + (lane >> 2);

    if (EPI == 0) {
#pragma unroll
        for (int mf = 0; mf < 4; mf++) {
#pragma unroll
            for (int half = 0; half < 2; half++) {
                int r = rbase + mf * 16 + half * 8;
                if (r >= rend) continue;
#pragma unroll
                for (int nf = 0; nf < 4; nf++) {
                    int c = col0 + warp_n * 32 + nf * 8 + (lane & 3) * 2;
                    float v0 = fmaxf(acc[mf][nf][half * 2 + 0] + bv[nf][0], 0.f);
                    float v1 = fmaxf(acc[mf][nf][half * 2 + 1] + bv[nf][1], 0.f);
                    *(__half2*)(g_h1 + (size_t)r * DH + c) = __floats2half2_rn(v0, v1);
                }
            }
        }
    } else {
#pragma unroll
        for (int nf = 0; nf < 4; nf++) {
            float s0 = 0.f, s1 = 0.f;
#pragma unroll
            for (int mf = 0; mf < 4; mf++) {
                int r0 = rbase + mf * 16;
                int r1 = r0 + 8;
                if (r0 < rend) {
                    s0 += fmaxf(acc[mf][nf][0] + bv[nf][0], 0.f);
                    s1 += fmaxf(acc[mf][nf][1] + bv[nf][1], 0.f);
                }
                if (r1 < rend) {
                    s0 += fmaxf(acc[mf][nf][2] + bv[nf][0], 0.f);
                    s1 += fmaxf(acc[mf][nf][3] + bv[nf][1], 0.f);
                }
            }
#pragma unroll
            for (int off = 16; off >= 4; off >>= 1) {
                s0 += __shfl_xor_sync(0xffffffffu, s0, off);
                s1 += __shfl_xor_sync(0xffffffffu, s1, off);
            }
            if (lane < 4) {
                int c = col0 + warp_n * 32 + nf * 8 + lane * 2;
                atomicAdd(&g_psum[k * DH + c], s0);
                atomicAdd(&g_psum[k * DH + c + 1], s1);
            }
        }
    }
}

// ---------------- parallel head ----------------
__global__ __launch_bounds__(256) void k_headB(const float* __restrict__ fc_W,
                                               const float* __restrict__ fc_b,
                                               const float* __restrict__ bc) {
    int gt = blockIdx.x * 256 + threadIdx.x;
    if (gt < KC) g_Alog[gt] = bc[0];
    int wid = gt >> 5;
    int lane = threadIdx.x & 31;
    if (wid >= KC * DH) return;
    int k = wid / DH, j = wid % DH;
    int cnt = g_cnt[k];
    float inv = (cnt > 0) ? 1.f / (float)cnt : 0.f;
    const float* pr = g_psum + k * DH;
    float s = 0.f;
#pragma unroll
    for (int t = 0; t < DH / 32; t++) {
        int i = t * 32 + lane;
        s += pr[i] * __ldg(fc_W + (size_t)i * DH + j);
    }
#pragma unroll
    for (int off = 16; off > 0; off >>= 1) s += __shfl_xor_sync(0xffffffffu, s, off);
    if (lane == 0) g_hs[k * DH + j] = fmaxf(s * inv + __ldg(fc_b + j), 0.f);
}

__global__ __launch_bounds__(256) void k_headC(const float* __restrict__ Va, const float* __restrict__ ba,
                                               const float* __restrict__ Vb, const float* __restrict__ bb,
                                               const float* __restrict__ Vc) {
    int wid = (blockIdx.x * 256 + threadIdx.x) >> 5;
    int lane = threadIdx.x & 31;
    if (wid >= KC * DA) return;
    int k = wid / DA, m = wid % DA;
    const float* hr = g_hs + k * DH;
    float sa = 0.f, sb = 0.f;
#pragma unroll
    for (int t = 0; t < DH / 32; t++) {
        int j = t * 32 + lane;
        float hv = hr[j];
        sa += hv * __ldg(Va + (size_t)j * DA + m);
        sb += hv * __ldg(Vb + (size_t)j * DA + m);
    }
#pragma unroll
    for (int off = 16; off > 0; off >>= 1) {
        sa += __shfl_xor_sync(0xffffffffu, sa, off);
        sb += __shfl_xor_sync(0xffffffffu, sb, off);
    }
    if (lane == 0) {
        float contrib = tanhf(sa + __ldg(ba + m)) * (1.f / (1.f + expf(-(sb + __ldg(bb + m))))) * __ldg(Vc + m);
        atomicAdd(&g_Alog[k], contrib);
    }
}

__global__ __launch_bounds__(512) void k_tail(const float* __restrict__ rho_W, const float* __restrict__ rho_b,
                                              const float* __restrict__ cls_W, const float* __restrict__ cls_b,
                                              float* __restrict__ out, int out_size) {
    __shared__ float attw[KC];
    __shared__ float hpath[DH];
    __shared__ float part[2][DA];
    __shared__ float hp2[DA];
    __shared__ float logits_s[NCLS];
    int tid = threadIdx.x;

    if (tid == 0) {
        float mx = -1e30f;
        float al[KC];
        for (int k = 0; k < KC; k++) { al[k] = g_Alog[k]; mx = fmaxf(mx, al[k]); }
        float s = 0.f;
        for (int k = 0; k < KC; k++) { float e = expf(al[k] - mx); attw[k] = e; s += e; }
        float inv = 1.f / s;
        for (int k = 0; k < KC; k++) attw[k] *= inv;
    }
    __syncthreads();

    {
        float s = 0.f;
#pragma unroll
        for (int k = 0; k < KC; k++) s += attw[k] * g_hs[k * DH + tid];
        hpath[tid] = s;
    }
    __syncthreads();

    {
        int m = tid & 255, half = tid >> 8;
        float s = 0.f;
#pragma unroll 8
        for (int j = half * 256; j < half * 256 + 256; j++)
            s += hpath[j] * __ldg(rho_W + (size_t)j * DA + m);
        part[half][m] = s;
    }
    __syncthreads();
    if (tid < DA) hp2[tid] = fmaxf(part[0][tid] + part[1][tid] + __ldg(rho_b + tid), 0.f);
    __syncthreads();

    if (tid < 128) {
        int c = tid >> 5, lane = tid & 31;
        float s = 0.f;
#pragma unroll
        for (int t = 0; t < DA / 32; t++) {
            int m = t * 32 + lane;
            s += hp2[m] * __ldg(cls_W + m * NCLS + c);
        }
#pragma unroll
        for (int off = 16; off > 0; off >>= 1) s += __shfl_xor_sync(0xffffffffu, s, off);
        if (lane == 0) logits_s[c] = s + __ldg(cls_b + c);
    }
    __syncthreads();

    if (tid == 0) {
        float haz[NCLS], S[NCLS];
        float run = 1.f;
        int best = 0;
        float bval = logits_s[0];
        for (int c = 0; c < NCLS; c++) {
            if (logits_s[c] > bval) { bval = logits_s[c]; best = c; }
            haz[c] = 1.f / (1.f + expf(-logits_s[c]));
            run *= (1.f - haz[c]);
            S[c] = run;
        }
        float vals[9];
        for (int c = 0; c < NCLS; c++) vals[c] = haz[c];
        for (int c = 0; c < NCLS; c++) vals[NCLS + c] = S[c];
        vals[8] = (float)best;
        for (int i = 0; i < out_size && i < 9; i++) out[i] = vals[i];
    }
    for (int i = 9 + tid; i < out_size; i += 512) out[i] = 0.f;
}

// ---------------- launch ----------------
extern "C" void kernel_launch(void* const* d_in, const int* in_sizes, int n_in,
                              void* d_out, int out_size) {
    const float* x     = (const float*)d_in[0];
    const int*   cid   = (const int*)d_in[1];
    const float* W1    = (const float*)d_in[2];
    const float* b1    = (const float*)d_in[3];
    const float* W2    = (const float*)d_in[4];
    const float* b2    = (const float*)d_in[5];
    const float* fc_W  = (const float*)d_in[6];
    const float* fc_b  = (const float*)d_in[7];
    const float* Va    = (const float*)d_in[8];
    const float* ba    = (const float*)d_in[9];
    const float* Vb    = (const float*)d_in[10];
    const float* bb    = (const float*)d_in[11];
    const float* Vc    = (const float*)d_in[12];
    const float* bc    = (const float*)d_in[13];
    const float* rho_W = (const float*)d_in[14];
    const float* rho_b = (const float*)d_in[15];
    const float* cls_W = (const float*)d_in[16];
    const float* cls_b = (const float*)d_in[17];
    float* out = (float*)d_out;

    int n = in_sizes[0] / DIN;   // 8192

    k_prep<<<1, 1024>>>(cid, n);                                      // 1
    {
        dim3 b(32, 8);
        k_conv_w_all<<<dim3(48, DH / 32, KC), b>>>(W1, W2);           // 2
    }

    dim3 grid(DH / 128, (n + 127) / 128, KC);
    k_mma<DIN, 0><<<grid, 256>>>(b1, x);                              // 3  (A = fp32 x, fused convert)
    k_mma<DH, 1><<<grid, 256>>>(b2, nullptr);                         // 4

    k_headB<<<(KC * DH * 32 + 255) / 256, 256>>>(fc_W, fc_b, bc);     // 5
    k_headC<<<(KC * DA * 32 + 255) / 256, 256>>>(Va, ba, Vb, bb, Vc); // 6
    k_tail<<<1, 512>>>(rho_W, rho_b, cls_W, cls_b, out, out_size);    // 7
}

// round 16
// speedup vs baseline: 1.0048x; 1.0048x over previous
#include <cuda_runtime.h>
#include <cuda_fp16.h>
#include <math.h>
#include <stdint.h>

#define NPATCH 8192
#define NPAD   (NPATCH + 128)
#define KC     10
#define DIN    1024
#define DH     512
#define DA     256
#define NCLS   4

// ---------------- device scratch (ONLY referenced inside device code) ----------------
__device__ int   g_cnt[KC];
__device__ int   g_off[KC + 1];
__device__ int   g_order[NPATCH];
__device__ __align__(128) __half g_w1t[(size_t)KC * DH * DIN];
__device__ __align__(128) __half g_w2t[(size_t)KC * DH * DH];
__device__ __align__(128) __half g_h1 [(size_t)NPAD * DH];
__device__ float g_psum[KC * DH];
__device__ float g_hs[KC * DH];
__device__ float g_Alog[KC];

// ---------------- PTX helpers ----------------
__device__ __forceinline__ uint32_t smem_u32(const void* p) {
    uint32_t a;
    asm("{ .reg .u64 t; cvta.to.shared.u64 t, %1; cvt.u32.u64 %0, t; }" : "=r"(a) : "l"(p));
    return a;
}
#define CPASYNC16(dst, src) asm volatile("cp.async.ca.shared.global [%0], [%1], 16;" :: "r"(dst), "l"(src) : "memory")
#define CP_COMMIT()         asm volatile("cp.async.commit_group;" ::: "memory")
#define CP_WAIT(n)          asm volatile("cp.async.wait_group %0;" :: "n"(n) : "memory")

__device__ __forceinline__ void ldsm4(uint32_t& r0, uint32_t& r1, uint32_t& r2, uint32_t& r3,
                                      uint32_t addr) {
    asm volatile("ldmatrix.sync.aligned.m8n8.x4.shared.b16 {%0,%1,%2,%3}, [%4];"
                 : "=r"(r0), "=r"(r1), "=r"(r2), "=r"(r3) : "r"(addr));
}
__device__ __forceinline__ void mma_f16(float* c, uint32_t a0, uint32_t a1, uint32_t a2,
                                        uint32_t a3, uint32_t b0, uint32_t b1) {
    asm volatile("mma.sync.aligned.m16n8k16.row.col.f32.f16.f16.f32 "
                 "{%0,%1,%2,%3}, {%4,%5,%6,%7}, {%8,%9}, {%0,%1,%2,%3};"
                 : "+f"(c[0]), "+f"(c[1]), "+f"(c[2]), "+f"(c[3])
                 : "r"(a0), "r"(a1), "r"(a2), "r"(a3), "r"(b0), "r"(b1));
}
__device__ __forceinline__ uint32_t packh2(float a, float b) {
    __half2 h = __floats2half2_rn(a, b);
    return *(uint32_t*)&h;
}

// ---------------- fused prep: hist + offsets + scatter + zero psum (single block) ----------
__global__ __launch_bounds__(1024) void k_prep(const int* __restrict__ cid, int n) {
    __shared__ int scnt[KC];
    __shared__ int scur[KC];
    int tid = threadIdx.x;
    if (tid < KC) scnt[tid] = 0;
    __syncthreads();
    for (int i = tid; i < n; i += 1024) atomicAdd(&scnt[cid[i]], 1);
    __syncthreads();
    if (tid == 0) {
        int s = 0;
        g_off[0] = 0;
        for (int k = 0; k < KC; k++) {
            g_cnt[k] = scnt[k];
            scur[k] = s;
            s += scnt[k];
            g_off[k + 1] = s;
        }
    }
    __syncthreads();
    for (int i = tid; i < n; i += 1024) {
        int c = cid[i];
        int pos = atomicAdd(&scur[c], 1);
        g_order[pos] = i;
    }
    for (int i = tid; i < KC * DH; i += 1024) g_psum[i] = 0.f;
}

// fused transpose+convert of BOTH weight tensors in one launch
// blockIdx.x in [0,32): W1 k-tile; [32,48): W2 k-tile. blockIdx.y: n-tile (16). z: cluster.
__global__ void k_conv_w_all(const float* __restrict__ W1, const float* __restrict__ W2) {
    int bx = blockIdx.x;
    int isW1 = bx < 32;
    const int KD = isW1 ? DIN : DH;
    const float* W = isW1 ? W1 : W2;
    __half* out = isW1 ? g_w1t : g_w2t;
    int kk0 = (isW1 ? bx : bx - 32) * 32;

    __shared__ float t[32][33];
    int tx = threadIdx.x, ty = threadIdx.y;
    int n0 = blockIdx.y * 32, k = blockIdx.z;
    const float* src = W + (size_t)k * KD * DH;
#pragma unroll
    for (int i = 0; i < 4; i++) {
        int row = ty + i * 8;
        t[row][tx] = src[(size_t)(kk0 + row) * DH + n0 + tx];
    }
    __syncthreads();
    __half* dst = out + (size_t)k * DH * KD;
#pragma unroll
    for (int i = 0; i < 4; i++) {
        int row = ty + i * 8;
        dst[(size_t)(n0 + row) * KD + kk0 + tx] = __float2half_rn(t[tx][row]);
    }
}

// ---------------- HMMA grouped GEMM ----------------
// EPI = 0: A = fp32 x gathered+converted in-loader; out g_h1 = fp16(relu(acc+bias))
// EPI = 1: A = g_h1 (fp16, cp.async);           out psum += colsum(relu(acc+bias))
#define LDA 40

template <int KDIM, int EPI>
__global__ __launch_bounds__(256, 2) void k_mma(const float* __restrict__ bias,
                                                const float* __restrict__ xsrc) {
    const __half* Bsrc = (EPI == 0) ? g_w1t : g_w2t;

    int k = blockIdx.z;
    int rend = g_off[k + 1];
    int row0 = g_off[k] + blockIdx.y * 128;
    if (row0 >= rend) return;
    int col0 = blockIdx.x * 128;

    __shared__ __align__(16) __half sA[2][128 * LDA];
    __shared__ __align__(16) __half sB[2][128 * LDA];

    int tid = threadIdx.x;
    int wid = tid >> 5, lane = tid & 31;
    int warp_m = wid & 1;
    int warp_n = wid >> 1;

    float acc[4][4][4];
#pragma unroll
    for (int mf = 0; mf < 4; mf++)
#pragma unroll
        for (int nf = 0; nf < 4; nf++)
#pragma unroll
            for (int q = 0; q < 4; q++) acc[mf][nf][q] = 0.f;

    int lrow = tid >> 1, lhalf = tid & 1;
    uint32_t aSm[2] = {smem_u32(&sA[0][0]), smem_u32(&sA[1][0])};
    uint32_t bSm[2] = {smem_u32(&sB[0][0]), smem_u32(&sB[1][0])};

    // B loader (cp.async), same for both
    uint32_t ldOff[2];
    const __half* bSrcQ[2];
#pragma unroll
    for (int q = 0; q < 2; q++) {
        int seg = lhalf * 2 + q;
        ldOff[q] = (uint32_t)(lrow * LDA + seg * 8) * 2;
        bSrcQ[q] = Bsrc + ((size_t)k * DH + col0 + lrow) * KDIM + seg * 8;
    }

    // A loader sources
    int arow = row0 + lrow;
    int arow_cl = (arow < rend) ? arow : (rend - 1);
    const float4* xq = nullptr;       // EPI==0: fp32 gathered
    const __half* aSrcQ[2] = {nullptr, nullptr};  // EPI==1: fp16 direct
    if (EPI == 0) {
        xq = (const float4*)(xsrc + (size_t)g_order[arow_cl] * DIN + lhalf * 16);
    } else {
#pragma unroll
        for (int q = 0; q < 2; q++) {
            int seg = lhalf * 2 + q;
            aSrcQ[q] = g_h1 + (size_t)arow * KDIM + seg * 8;
        }
    }
    __half* aSts = &sA[0][0] + (lrow * LDA + lhalf * 16);   // buf0 base; buf1 = +128*LDA

    int lane15 = lane & 15, lanehi = lane >> 4;
    uint32_t offA[4], offB[2];
#pragma unroll
    for (int mf = 0; mf < 4; mf++)
        offA[mf] = (uint32_t)((warp_m * 64 + mf * 16 + lane15) * LDA + lanehi * 8) * 2;
#pragma unroll
    for (int ng = 0; ng < 2; ng++)
        offB[ng] = (uint32_t)((warp_n * 32 + ng * 16 + lane15) * LDA + lanehi * 8) * 2;

    const int NCH = KDIM / 32;

    auto compute = [&](int buf) {
#pragma unroll
        for (int ks = 0; ks < 2; ks++) {
            uint32_t kof = ks * 32;
            uint32_t afr[4][4], bfr[4][2];
#pragma unroll
            for (int mf = 0; mf < 4; mf++)
                ldsm4(afr[mf][0], afr[mf][1], afr[mf][2], afr[mf][3], aSm[buf] + offA[mf] + kof);
#pragma unroll
            for (int ng = 0; ng < 2; ng++) {
                uint32_t r0, r1, r2, r3;
                ldsm4(r0, r1, r2, r3, bSm[buf] + offB[ng] + kof);
                bfr[ng * 2 + 0][0] = r0; bfr[ng * 2 + 0][1] = r2;
                bfr[ng * 2 + 1][0] = r1; bfr[ng * 2 + 1][1] = r3;
            }
#pragma unroll
            for (int mf = 0; mf < 4; mf++)
#pragma unroll
                for (int nf = 0; nf < 4; nf++)
                    mma_f16(acc[mf][nf], afr[mf][0], afr[mf][1], afr[mf][2], afr[mf][3],
                            bfr[nf][0], bfr[nf][1]);
        }
    };

    if (EPI == 0) {
        // ---- A: fp32 LDG + convert + STS (register prefetch); B: cp.async ----
        float4 fa[4];
#pragma unroll
        for (int q = 0; q < 4; q++) fa[q] = __ldg(xq + q);
#pragma unroll
        for (int q = 0; q < 2; q++) CPASYNC16(bSm[0] + ldOff[q], bSrcQ[q]);
        CP_COMMIT();

        for (int s = 0; s < NCH; s++) {
            int buf = s & 1;
            {   // convert + store current A chunk
                uint32_t hw[8];
#pragma unroll
                for (int q = 0; q < 4; q++) {
                    hw[2 * q + 0] = packh2(fa[q].x, fa[q].y);
                    hw[2 * q + 1] = packh2(fa[q].z, fa[q].w);
                }
                uint4* d = (uint4*)(aSts + buf * 128 * LDA);
                d[0] = make_uint4(hw[0], hw[1], hw[2], hw[3]);
                d[1] = make_uint4(hw[4], hw[5], hw[6], hw[7]);
            }
            if (s + 1 < NCH) {
                int nb = (s + 1) & 1;
#pragma unroll
                for (int q = 0; q < 2; q++)
                    CPASYNC16(bSm[nb] + ldOff[q], bSrcQ[q] + (size_t)(s + 1) * 32);
                CP_COMMIT();
                CP_WAIT(1);
            } else {
                CP_WAIT(0);
            }
            __syncthreads();
            if (s + 1 < NCH) {
#pragma unroll
                for (int q = 0; q < 4; q++) fa[q] = __ldg(xq + (s + 1) * 8 + q);
            }
            compute(buf);
            __syncthreads();
        }
    } else {
        // ---- both A and B via cp.async (A rows already cluster-sorted in g_h1) ----
#pragma unroll
        for (int q = 0; q < 2; q++) {
            CPASYNC16(aSm[0] + ldOff[q], aSrcQ[q]);
            CPASYNC16(bSm[0] + ldOff[q], bSrcQ[q]);
        }
        CP_COMMIT();

        for (int s = 0; s < NCH; s++) {
            int buf = s & 1;
            if (s + 1 < NCH) {
                int nb = (s + 1) & 1;
#pragma unroll
                for (int q = 0; q < 2; q++) {
                    CPASYNC16(aSm[nb] + ldOff[q], aSrcQ[q] + (size_t)(s + 1) * 32);
                    CPASYNC16(bSm[nb] + ldOff[q], bSrcQ[q] + (size_t)(s + 1) * 32);
                }
                CP_COMMIT();
                CP_WAIT(1);
            } else {
                CP_WAIT(0);
            }
            __syncthreads();
            compute(buf);
            __syncthreads();
        }
    }

    // ---------------- epilogue ----------------
    const float* bp = bias + k * DH + col0 + warp_n * 32;
    float bv[4][2];
#pragma unroll
    for (int nf = 0; nf < 4; nf++) {
        bv[nf][0] = __ldg(bp + nf * 8 + (lane & 3) * 2);
        bv[nf][1] = __ldg(bp + nf * 8 + (lane & 3) * 2 + 1);
    }
    int rbase = row0 + warp_m * 64 + (lane >> 2);

    if (EPI == 0) {
#pragma unroll
        for (int mf = 0; mf < 4; mf++) {
#pragma unroll
            for (int half = 0; half < 2; half++) {
                int r = rbase + mf * 16 + half * 8;
                if (r >= rend) continue;
#pragma unroll
                for (int nf = 0; nf < 4; nf++) {
                    int c = col0 + warp_n * 32 + nf * 8 + (lane & 3) * 2;
                    float v0 = fmaxf(acc[mf][nf][half * 2 + 0] + bv[nf][0], 0.f);
                    float v1 = fmaxf(acc[mf][nf][half * 2 + 1] + bv[nf][1], 0.f);
                    *(__half2*)(g_h1 + (size_t)r * DH + c) = __floats2half2_rn(v0, v1);
                }
            }
        }
    } else {
#pragma unroll
        for (int nf = 0; nf < 4; nf++) {
            float s0 = 0.f, s1 = 0.f;
#pragma unroll
            for (int mf = 0; mf < 4; mf++) {
                int r0 = rbase + mf * 16;
                int r1 = r0 + 8;
                if (r0 < rend) {
                    s0 += fmaxf(acc[mf][nf][0] + bv[nf][0], 0.f);
                    s1 += fmaxf(acc[mf][nf][1] + bv[nf][1], 0.f);
                }
                if (r1 < rend) {
                    s0 += fmaxf(acc[mf][nf][2] + bv[nf][0], 0.f);
                    s1 += fmaxf(acc[mf][nf][3] + bv[nf][1], 0.f);
                }
            }
#pragma unroll
            for (int off = 16; off >= 4; off >>= 1) {
                s0 += __shfl_xor_sync(0xffffffffu, s0, off);
                s1 += __shfl_xor_sync(0xffffffffu, s1, off);
            }
            if (lane < 4) {
                int c = col0 + warp_n * 32 + nf * 8 + lane * 2;
                atomicAdd(&g_psum[k * DH + c], s0);
                atomicAdd(&g_psum[k * DH + c + 1], s1);
            }
        }
    }
}

// ---------------- parallel head ----------------
__global__ __launch_bounds__(256) void k_headB(const float* __restrict__ fc_W,
                                               const float* __restrict__ fc_b,
                                               const float* __restrict__ bc) {
    int gt = blockIdx.x * 256 + threadIdx.x;
    if (gt < KC) g_Alog[gt] = bc[0];
    int wid = gt >> 5;
    int lane = threadIdx.x & 31;
    if (wid >= KC * DH) return;
    int k = wid / DH, j = wid % DH;
    int cnt = g_cnt[k];
    float inv = (cnt > 0) ? 1.f / (float)cnt : 0.f;
    const float* pr = g_psum + k * DH;
    float s = 0.f;
#pragma unroll
    for (int t = 0; t < DH / 32; t++) {
        int i = t * 32 + lane;
        s += pr[i] * __ldg(fc_W + (size_t)i * DH + j);
    }
#pragma unroll
    for (int off = 16; off > 0; off >>= 1) s += __shfl_xor_sync(0xffffffffu, s, off);
    if (lane == 0) g_hs[k * DH + j] = fmaxf(s * inv + __ldg(fc_b + j), 0.f);
}

__global__ __launch_bounds__(256) void k_headC(const float* __restrict__ Va, const float* __restrict__ ba,
                                               const float* __restrict__ Vb, const float* __restrict__ bb,
                                               const float* __restrict__ Vc) {
    int wid = (blockIdx.x * 256 + threadIdx.x) >> 5;
    int lane = threadIdx.x & 31;
    if (wid >= KC * DA) return;
    int k = wid / DA, m = wid % DA;
    const float* hr = g_hs + k * DH;
    float sa = 0.f, sb = 0.f;
#pragma unroll
    for (int t = 0; t < DH / 32; t++) {
        int j = t * 32 + lane;
        float hv = hr[j];
        sa += hv * __ldg(Va + (size_t)j * DA + m);
        sb += hv * __ldg(Vb + (size_t)j * DA + m);
    }
#pragma unroll
    for (int off = 16; off > 0; off >>= 1) {
        sa += __shfl_xor_sync(0xffffffffu, sa, off);
        sb += __shfl_xor_sync(0xffffffffu, sb, off);
    }
    if (lane == 0) {
        float contrib = tanhf(sa + __ldg(ba + m)) * (1.f / (1.f + expf(-(sb + __ldg(bb + m))))) * __ldg(Vc + m);
        atomicAdd(&g_Alog[k], contrib);
    }
}

__global__ __launch_bounds__(512) void k_tail(const float* __restrict__ rho_W, const float* __restrict__ rho_b,
                                              const float* __restrict__ cls_W, const float* __restrict__ cls_b,
                                              float* __restrict__ out, int out_size) {
    __shared__ float attw[KC];
    __shared__ float hpath[DH];
    __shared__ float part[2][DA];
    __shared__ float hp2[DA];
    __shared__ float logits_s[NCLS];
    int tid = threadIdx.x;

    if (tid == 0) {
        float mx = -1e30f;
        float al[KC];
        for (int k = 0; k < KC; k++) { al[k] = g_Alog[k]; mx = fmaxf(mx, al[k]); }
        float s = 0.f;
        for (int k = 0; k < KC; k++) { float e = expf(al[k] - mx); attw[k] = e; s += e; }
        float inv = 1.f / s;
        for (int k = 0; k < KC; k++) attw[k] *= inv;
    }
    __syncthreads();

    {
        float s = 0.f;
#pragma unroll
        for (int k = 0; k < KC; k++) s += attw[k] * g_hs[k * DH + tid];
        hpath[tid] = s;
    }
    __syncthreads();

    {
        int m = tid & 255, half = tid >> 8;
        float s = 0.f;
#pragma unroll 8
        for (int j = half * 256; j < half * 256 + 256; j++)
            s += hpath[j] * __ldg(rho_W + (size_t)j * DA + m);
        part[half][m] = s;
    }
    __syncthreads();
    if (tid < DA) hp2[tid] = fmaxf(part[0][tid] + part[1][tid] + __ldg(rho_b + tid), 0.f);
    __syncthreads();

    if (tid < 128) {
        int c = tid >> 5, lane = tid & 31;
        float s = 0.f;
#pragma unroll
        for (int t = 0; t < DA / 32; t++) {
            int m = t * 32 + lane;
            s += hp2[m] * __ldg(cls_W + m * NCLS + c);
        }
#pragma unroll
        for (int off = 16; off > 0; off >>= 1) s += __shfl_xor_sync(0xffffffffu, s, off);
        if (lane == 0) logits_s[c] = s + __ldg(cls_b + c);
    }
    __syncthreads();

    if (tid == 0) {
        float haz[NCLS], S[NCLS];
        float run = 1.f;
        int best = 0;
        float bval = logits_s[0];
        for (int c = 0; c < NCLS; c++) {
            if (logits_s[c] > bval) { bval = logits_s[c]; best = c; }
            haz[c] = 1.f / (1.f + expf(-logits_s[c]));
            run *= (1.f - haz[c]);
            S[c] = run;
        }
        float vals[9];
        for (int c = 0; c < NCLS; c++) vals[c] = haz[c];
        for (int c = 0; c < NCLS; c++) vals[NCLS + c] = S[c];
        vals[8] = (float)best;
        for (int i = 0; i < out_size && i < 9; i++) out[i] = vals[i];
    }
    for (int i = 9 + tid; i < out_size; i += 512) out[i] = 0.f;
}

// ---------------- launch ----------------
extern "C" void kernel_launch(void* const* d_in, const int* in_sizes, int n_in,
                              void* d_out, int out_size) {
    const float* x     = (const float*)d_in[0];
    const int*   cid   = (const int*)d_in[1];
    const float* W1    = (const float*)d_in[2];
    const float* b1    = (const float*)d_in[3];
    const float* W2    = (const float*)d_in[4];
    const float* b2    = (const float*)d_in[5];
    const float* fc_W  = (const float*)d_in[6];
    const float* fc_b  = (const float*)d_in[7];
    const float* Va    = (const float*)d_in[8];
    const float* ba    = (const float*)d_in[9];
    const float* Vb    = (const float*)d_in[10];
    const float* bb    = (const float*)d_in[11];
    const float* Vc    = (const float*)d_in[12];
    const float* bc    = (const float*)d_in[13];
    const float* rho_W = (const float*)d_in[14];
    const float* rho_b = (const float*)d_in[15];
    const float* cls_W = (const float*)d_in[16];
    const float* cls_b = (const float*)d_in[17];
    float* out = (float*)d_out;

    int n = in_sizes[0] / DIN;   // 8192

    k_prep<<<1, 1024>>>(cid, n);                                      // 1
    {
        dim3 b(32, 8);
        k_conv_w_all<<<dim3(48, DH / 32, KC), b>>>(W1, W2);           // 2
    }

    dim3 grid(DH / 128, (n + 127) / 128, KC);
    k_mma<DIN, 0><<<grid, 256>>>(b1, x);                              // 3  (A = fp32 x, fused convert)
    k_mma<DH, 1><<<grid, 256>>>(b2, nullptr);                         // 4

    k_headB<<<(KC * DH * 32 + 255) / 256, 256>>>(fc_W, fc_b, bc);     // 5
    k_headC<<<(KC * DA * 32 + 255) / 256, 256>>>(Va, ba, Vb, bb, Vc); // 6
    k_tail<<<1, 512>>>(rho_W, rho_b, cls_W, cls_b, out, out_size);    // 7
}